// round 3
// baseline (speedup 1.0000x reference)
#include <cuda_runtime.h>
#include <cstdint>

// Problem constants
#define BB   64      // batch
#define TT   1024    // time steps
#define HH   256     // hidden per direction
#define DIN  136     // input features (68*2)
#define G4   1024    // 4*H
#define NBLK 64      // persistent blocks per direction
#define HB   (HH*BB) // 16384 floats of hidden state per direction

// ---------------- scratch (device globals; no allocations allowed) ----------------
__device__ __align__(16) float g_proj[2][(size_t)TT * G4 * BB]; // [dir][t][row][b]
__device__ __align__(16) float g_hs[(size_t)TT * 2 * HH * BB];  // [t][dir*H+j][b]
__device__ __align__(16) float g_hbuf[2][2][HB];                // [dir][parity][j][b]
__device__ unsigned g_bar_arrive[2];
__device__ unsigned g_bar_epoch[2];

// ---------------- packed f32x2 helpers ----------------
__device__ __forceinline__ void ffma2(unsigned long long& d, unsigned long long a,
                                      unsigned long long b) {
    asm("fma.rn.f32x2 %0, %1, %2, %0;" : "+l"(d) : "l"(a), "l"(b));
}
__device__ __forceinline__ unsigned long long pack2(float lo, float hi) {
    unsigned long long r;
    asm("mov.b64 %0, {%1, %2};" : "=l"(r) : "f"(lo), "f"(hi));
    return r;
}
__device__ __forceinline__ float2 unpack2(unsigned long long v) {
    float2 f;
    asm("mov.b64 {%0, %1}, %2;" : "=f"(f.x), "=f"(f.y) : "l"(v));
    return f;
}

// ---------------- activations ----------------
__device__ __forceinline__ float sigf(float x) {
    return 1.0f / (1.0f + __expf(-x));
}
__device__ __forceinline__ float tanh_fast(float x) {
    float xx = fminf(fmaxf(x, -10.0f), 10.0f);
    float e = __expf(2.0f * xx);
    return (e - 1.0f) / (e + 1.0f);
}

// ---------------- init: reset mutable state each launch (graph-replay safe) -------
__global__ void init_kernel() {
    int tid = threadIdx.x;
    float* hb = &g_hbuf[0][0][0];
    for (int i = tid; i < 2 * 2 * HB; i += 256) hb[i] = 0.0f;
    if (tid < 2) { g_bar_arrive[tid] = 0u; g_bar_epoch[tid] = 0u; }
}

// ---------------- input projection GEMM (f32x2: rows packed in pairs) -------------
// proj[dir][t][row][b] = b_ih[row] + sum_k x[b][t][k] * w_ih[row][k]
__global__ void __launch_bounds__(128, 2) proj_kernel(
    const float* __restrict__ x,
    const float* __restrict__ wih_f, const float* __restrict__ wih_b,
    const float* __restrict__ bih_f, const float* __restrict__ bih_b)
{
    extern __shared__ float sm[];
    float* xs = sm;               // [136][68] transposed: xs[k][b]
    float* ws = sm + 136 * 68;    // [136][68] transposed: ws[k][r]

    const int t   = blockIdx.y;
    const int dir = blockIdx.z;
    const int r0  = blockIdx.x * 64;
    const float* w  = dir ? wih_b : wih_f;
    const float* bi = dir ? bih_b : bih_f;
    const int tid = threadIdx.x;

    for (int i = tid; i < 64 * 34; i += 128) {
        int b = i / 34, k4 = i - b * 34;
        float4 v = __ldg(((const float4*)(x + ((size_t)b * TT + t) * DIN)) + k4);
        int kb = k4 * 4;
        xs[(kb + 0) * 68 + b] = v.x;
        xs[(kb + 1) * 68 + b] = v.y;
        xs[(kb + 2) * 68 + b] = v.z;
        xs[(kb + 3) * 68 + b] = v.w;
    }
    for (int i = tid; i < 64 * 34; i += 128) {
        int r = i / 34, k4 = i - r * 34;
        float4 v = __ldg(((const float4*)(w + (size_t)(r0 + r) * DIN)) + k4);
        int kb = k4 * 4;
        ws[(kb + 0) * 68 + r] = v.x;
        ws[(kb + 1) * 68 + r] = v.y;
        ws[(kb + 2) * 68 + r] = v.z;
        ws[(kb + 3) * 68 + r] = v.w;
    }
    __syncthreads();

    const int tx = tid & 15;   // b = tx*4 .. +3
    const int ty = tid >> 4;   // rows ty*8 .. +7 (as 4 row-pairs)

    unsigned long long accp[4][4];   // [row-pair][b]
#pragma unroll
    for (int q = 0; q < 4; q++)
#pragma unroll
        for (int j = 0; j < 4; j++) accp[q][j] = 0ull;

#pragma unroll 4
    for (int k = 0; k < DIN; k++) {
        float4 xv = *(const float4*)(xs + k * 68 + tx * 4);
        ulonglong2 wa = *(const ulonglong2*)(ws + k * 68 + ty * 8);      // {r01, r23}
        ulonglong2 wb = *(const ulonglong2*)(ws + k * 68 + ty * 8 + 4);  // {r45, r67}
        unsigned long long x0 = pack2(xv.x, xv.x);
        unsigned long long x1 = pack2(xv.y, xv.y);
        unsigned long long x2 = pack2(xv.z, xv.z);
        unsigned long long x3 = pack2(xv.w, xv.w);
        ffma2(accp[0][0], wa.x, x0); ffma2(accp[0][1], wa.x, x1);
        ffma2(accp[0][2], wa.x, x2); ffma2(accp[0][3], wa.x, x3);
        ffma2(accp[1][0], wa.y, x0); ffma2(accp[1][1], wa.y, x1);
        ffma2(accp[1][2], wa.y, x2); ffma2(accp[1][3], wa.y, x3);
        ffma2(accp[2][0], wb.x, x0); ffma2(accp[2][1], wb.x, x1);
        ffma2(accp[2][2], wb.x, x2); ffma2(accp[2][3], wb.x, x3);
        ffma2(accp[3][0], wb.y, x0); ffma2(accp[3][1], wb.y, x1);
        ffma2(accp[3][2], wb.y, x2); ffma2(accp[3][3], wb.y, x3);
    }

    float* dst = g_proj[dir] + (size_t)t * G4 * BB;
#pragma unroll
    for (int q = 0; q < 4; q++) {
        float2 v0 = unpack2(accp[q][0]);
        float2 v1 = unpack2(accp[q][1]);
        float2 v2 = unpack2(accp[q][2]);
        float2 v3 = unpack2(accp[q][3]);
        int rowa = r0 + ty * 8 + 2 * q;
        float ba = __ldg(bi + rowa);
        float bb = __ldg(bi + rowa + 1);
        *(float4*)(dst + (size_t)rowa * BB + tx * 4) =
            make_float4(v0.x + ba, v1.x + ba, v2.x + ba, v3.x + ba);
        *(float4*)(dst + (size_t)(rowa + 1) * BB + tx * 4) =
            make_float4(v0.y + bb, v1.y + bb, v2.y + bb, v3.y + bb);
    }
}

// ---------------- persistent recurrent scan (f32x2 over batch pairs) ---------------
// 128 blocks (64 fwd + 64 bwd), 256 threads, 1 CTA/SM.
// Block owns j' in [j0, j0+4): 16 W_hh rows pre-packed {w,w} in SMEM.
__global__ void __launch_bounds__(256, 1) scan_kernel(
    const float* __restrict__ whh_f, const float* __restrict__ whh_b,
    const float* __restrict__ bhh_f, const float* __restrict__ bhh_b)
{
    extern __shared__ float smem[];
    float* h_s = smem;             // [256][64] h transposed (64KB)
    float* red = smem + HB;        // [8][16][64] split-k partials (32KB)
    unsigned long long* wp = (unsigned long long*)(smem + HB + 8192); // [256][16] {w,w} (32KB)

    const int dir = blockIdx.x >> 6;
    const int blk = blockIdx.x & 63;
    const int j0  = blk * 4;
    const float* whh = dir ? whh_b : whh_f;
    const float* bhh = dir ? bhh_b : bhh_f;
    const int tid = threadIdx.x;

    // compute-phase mapping: warp = k-slice, lanes = 8 b-groups x 4 gates
    const int bg = tid & 7;          // b = bg*8 .. +7 (4 pairs)
    const int rg = (tid >> 3) & 3;   // gate index
    const int ks = tid >> 5;         // k-slice [ks*32, ks*32+32)

    // build packed W_hh table: wp[k*16 + rg*4 + q] = {w,w}, w = whh[rg*256+j0+q][k]
    for (int idx = tid; idx < 4096; idx += 256) {
        int k = idx >> 4, r = idx & 15;
        int rgg = r >> 2, q = r & 3;
        float v = __ldg(whh + (size_t)(rgg * 256 + j0 + q) * HH + k);
        wp[idx] = pack2(v, v);
    }

    // gate/state-phase mapping
    const int jj2 = tid >> 6;        // 0..3
    const int b2  = tid & 63;        // 0..63
    float bh[4];
#pragma unroll
    for (int g = 0; g < 4; g++) bh[g] = __ldg(bhh + g * 256 + j0 + jj2);

    float c = 0.0f;
    int p = 0;
    float* hbuf = &g_hbuf[dir][0][0];
    __syncthreads();

    for (int s = 0; s < TT; ++s) {
        const int t = dir ? (TT - 1 - s) : s;

        // prefetch x-projection gate values (overlaps k-loop)
        float pf[4];
#pragma unroll
        for (int g = 0; g < 4; g++)
            pf[g] = __ldg(g_proj[dir] + ((size_t)t * G4 + g * 256 + j0 + jj2) * BB + b2);

        // pull h_prev into SMEM (L2-coherent loads)
        {
            const float4* src = (const float4*)(hbuf + p * HB);
            float4* dst = (float4*)h_s;
#pragma unroll
            for (int i = 0; i < 16; i++)
                dst[tid + (i << 8)] = __ldcg(src + tid + (i << 8));
        }
        __syncthreads();

        // k-slice GEMM, batch pairs packed: acc[q][pb] (+= {w,w} * {h,h})
        unsigned long long acc[4][4];
#pragma unroll
        for (int q = 0; q < 4; q++)
#pragma unroll
            for (int i = 0; i < 4; i++) acc[q][i] = 0ull;

#pragma unroll
        for (int kk = 0; kk < 32; kk++) {
            const int k = (ks << 5) + kk;
            const ulonglong2* h2 = (const ulonglong2*)(h_s + k * 64 + (bg << 3));
            ulonglong2 ha = h2[0];           // pairs (b0b1),(b2b3)
            ulonglong2 hc = h2[1];           // pairs (b4b5),(b6b7)
            const ulonglong2* wv = (const ulonglong2*)(wp + k * 16 + (rg << 2));
            ulonglong2 w01 = wv[0];          // {w_q0, w_q1} (each {w,w})
            ulonglong2 w23 = wv[1];
            ffma2(acc[0][0], w01.x, ha.x); ffma2(acc[0][1], w01.x, ha.y);
            ffma2(acc[0][2], w01.x, hc.x); ffma2(acc[0][3], w01.x, hc.y);
            ffma2(acc[1][0], w01.y, ha.x); ffma2(acc[1][1], w01.y, ha.y);
            ffma2(acc[1][2], w01.y, hc.x); ffma2(acc[1][3], w01.y, hc.y);
            ffma2(acc[2][0], w23.x, ha.x); ffma2(acc[2][1], w23.x, ha.y);
            ffma2(acc[2][2], w23.x, hc.x); ffma2(acc[2][3], w23.x, hc.y);
            ffma2(acc[3][0], w23.y, ha.x); ffma2(acc[3][1], w23.y, ha.y);
            ffma2(acc[3][2], w23.y, hc.x); ffma2(acc[3][3], w23.y, hc.y);
        }

        // write split-k partials: red[ks][gate*4+q][b] (packed layout == scalar layout)
#pragma unroll
        for (int q = 0; q < 4; q++) {
            float* rp = red + ((ks << 4) + (rg << 2) + q) * 64 + (bg << 3);
            ulonglong2 u0; u0.x = acc[q][0]; u0.y = acc[q][1];
            ulonglong2 u1; u1.x = acc[q][2]; u1.y = acc[q][3];
            *(ulonglong2*)rp = u0;
            *(ulonglong2*)(rp + 4) = u1;
        }
        __syncthreads();

        // gate phase: reduce 8 partials per gate, apply LSTM cell
        float gv[4];
#pragma unroll
        for (int g = 0; g < 4; g++) {
            float v = pf[g] + bh[g];
#pragma unroll
            for (int wi = 0; wi < 8; wi++)
                v += red[((wi << 4) + (g << 2) + jj2) * 64 + b2];
            gv[g] = v;
        }
        float i_ = sigf(gv[0]);
        float f_ = sigf(gv[1]);
        float g_ = tanh_fast(gv[2]);
        float o_ = sigf(gv[3]);
        c = f_ * c + i_ * g_;
        float h = o_ * tanh_fast(c);

        // publish h for next step + store hidden sequence
        hbuf[(p ^ 1) * HB + (j0 + jj2) * 64 + b2] = h;
        g_hs[((size_t)t * 512 + dir * HH + j0 + jj2) * BB + b2] = h;

        // direction-local grid barrier (scoped acq/rel; avoids CCTL.IVALL of __threadfence)
        __syncthreads();
        if (tid == 0) {
            unsigned ticket;
            asm volatile("atom.global.add.acq_rel.gpu.u32 %0, [%1], 1;"
                         : "=r"(ticket) : "l"(&g_bar_arrive[dir]) : "memory");
            if (ticket == (unsigned)(s + 1) * NBLK - 1u) {
                asm volatile("st.global.release.gpu.u32 [%0], %1;"
                             :: "l"(&g_bar_epoch[dir]), "r"((unsigned)(s + 1)) : "memory");
            } else {
                unsigned e;
                do {
                    asm volatile("ld.global.acquire.gpu.u32 %0, [%1];"
                                 : "=r"(e) : "l"(&g_bar_epoch[dir]) : "memory");
                } while (e <= (unsigned)s);
            }
        }
        __syncthreads();
        p ^= 1;
    }
}

// ---------------- final FC ----------------
__global__ void __launch_bounds__(320) fc_kernel(
    const float* __restrict__ fcw, const float* __restrict__ fcb,
    float* __restrict__ out)
{
    const int t = blockIdx.x;
    const int o = threadIdx.x / 64;  // 0..4
    const int b = threadIdx.x & 63;  // 0..63
    const float* hp = g_hs + (size_t)t * 512 * BB + b;
    const float* wp = fcw + o * 512;
    float acc = 0.0f;
#pragma unroll 8
    for (int j = 0; j < 512; j++)
        acc += hp[(size_t)j * BB] * __ldg(wp + j);
    out[((size_t)b * TT + t) * 5 + o] = acc + __ldg(fcb + o);
}

// ---------------- launch ----------------
extern "C" void kernel_launch(void* const* d_in, const int* in_sizes, int n_in,
                              void* d_out, int out_size)
{
    const float* x      = (const float*)d_in[0];
    const float* wih_f  = (const float*)d_in[1];
    const float* whh_f  = (const float*)d_in[2];
    const float* bih_f  = (const float*)d_in[3];
    const float* bhh_f  = (const float*)d_in[4];
    const float* wih_b  = (const float*)d_in[5];
    const float* whh_b  = (const float*)d_in[6];
    const float* bih_b  = (const float*)d_in[7];
    const float* bhh_b  = (const float*)d_in[8];
    const float* fcw    = (const float*)d_in[9];
    const float* fcb    = (const float*)d_in[10];
    float* out = (float*)d_out;

    const int proj_smem = 2 * 136 * 68 * (int)sizeof(float);            // 73,984 B
    const int scan_smem = (HB + 8192) * (int)sizeof(float) + 4096 * 8;  // 131,072 B
    cudaFuncSetAttribute(proj_kernel, cudaFuncAttributeMaxDynamicSharedMemorySize, proj_smem);
    cudaFuncSetAttribute(scan_kernel, cudaFuncAttributeMaxDynamicSharedMemorySize, scan_smem);

    init_kernel<<<1, 256>>>();

    dim3 pg(16, TT, 2);
    proj_kernel<<<pg, 128, proj_smem>>>(x, wih_f, wih_b, bih_f, bih_b);

    scan_kernel<<<2 * NBLK, 256, scan_smem>>>(whh_f, whh_b, bhh_f, bhh_b);

    fc_kernel<<<TT, 320>>>(fcw, fcb, out);
}

// round 4
// speedup vs baseline: 1.0605x; 1.0605x over previous
#include <cuda_runtime.h>
#include <cstdint>

// Problem constants
#define BB   64      // batch
#define TT   1024    // time steps
#define HH   256     // hidden per direction
#define DIN  136     // input features (68*2)
#define G4   1024    // 4*H
#define NBLK 64      // persistent blocks per direction
#define HB   (HH*BB) // 16384 floats of hidden state per direction

// ---------------- scratch (device globals; no allocations allowed) ----------------
__device__ __align__(16) float g_proj[2][(size_t)TT * G4 * BB]; // [dir][t][row][b]
__device__ __align__(16) float g_hs[(size_t)TT * 2 * HH * BB];  // [t][dir*H+j][b]
__device__ __align__(16) float g_hbuf[2][2][HB];                // [dir][parity][j][b]
__device__ __align__(128) unsigned g_flags[2][NBLK][32];        // 128B-strided epoch flags

// ---------------- packed f32x2 helpers ----------------
__device__ __forceinline__ void ffma2(unsigned long long& d, unsigned long long a,
                                      unsigned long long b) {
    asm("fma.rn.f32x2 %0, %1, %2, %0;" : "+l"(d) : "l"(a), "l"(b));
}
__device__ __forceinline__ unsigned long long pack_dup(float v) {
    unsigned long long r;
    asm("mov.b64 %0, {%1, %1};" : "=l"(r) : "f"(v));
    return r;
}

// ---------------- cp.async 16B (L2-coherent, bypasses L1) ----------------
__device__ __forceinline__ void cp_async16(float* smem_dst, const float* gsrc) {
    uint32_t s = (uint32_t)__cvta_generic_to_shared(smem_dst);
    asm volatile("cp.async.cg.shared.global [%0], [%1], 16;" :: "r"(s), "l"(gsrc));
}

// ---------------- activations ----------------
__device__ __forceinline__ float sigf(float x) {
    return 1.0f / (1.0f + __expf(-x));
}
__device__ __forceinline__ float tanh_fast(float x) {
    float xx = fminf(fmaxf(x, -10.0f), 10.0f);
    float e = __expf(2.0f * xx);
    return (e - 1.0f) / (e + 1.0f);
}

// ---------------- init: reset mutable state each launch (graph-replay safe) -------
__global__ void init_kernel() {
    int tid = threadIdx.x;
    float* hb = &g_hbuf[0][0][0];
    for (int i = tid; i < 2 * 2 * HB; i += 256) hb[i] = 0.0f;
    unsigned* fl = &g_flags[0][0][0];
    for (int i = tid; i < 2 * NBLK * 32; i += 256) fl[i] = 0u;
}

// ---------------- input projection GEMM (R1 version, known-good) ------------------
__global__ void __launch_bounds__(128, 2) proj_kernel(
    const float* __restrict__ x,
    const float* __restrict__ wih_f, const float* __restrict__ wih_b,
    const float* __restrict__ bih_f, const float* __restrict__ bih_b)
{
    extern __shared__ float sm[];
    float* xs = sm;               // [136][68] transposed: xs[k][b]
    float* ws = sm + 136 * 68;    // [136][68] transposed: ws[k][r]

    const int t   = blockIdx.y;
    const int dir = blockIdx.z;
    const int r0  = blockIdx.x * 64;
    const float* w  = dir ? wih_b : wih_f;
    const float* bi = dir ? bih_b : bih_f;
    const int tid = threadIdx.x;

    for (int i = tid; i < 64 * 34; i += 128) {
        int b = i / 34, k4 = i - b * 34;
        float4 v = __ldg(((const float4*)(x + ((size_t)b * TT + t) * DIN)) + k4);
        int kb = k4 * 4;
        xs[(kb + 0) * 68 + b] = v.x;
        xs[(kb + 1) * 68 + b] = v.y;
        xs[(kb + 2) * 68 + b] = v.z;
        xs[(kb + 3) * 68 + b] = v.w;
    }
    for (int i = tid; i < 64 * 34; i += 128) {
        int r = i / 34, k4 = i - r * 34;
        float4 v = __ldg(((const float4*)(w + (size_t)(r0 + r) * DIN)) + k4);
        int kb = k4 * 4;
        ws[(kb + 0) * 68 + r] = v.x;
        ws[(kb + 1) * 68 + r] = v.y;
        ws[(kb + 2) * 68 + r] = v.z;
        ws[(kb + 3) * 68 + r] = v.w;
    }
    __syncthreads();

    const int tx = tid & 15;
    const int ty = tid >> 4;
    float acc[8][4];
#pragma unroll
    for (int q = 0; q < 8; q++)
#pragma unroll
        for (int j = 0; j < 4; j++) acc[q][j] = 0.0f;

#pragma unroll 4
    for (int k = 0; k < DIN; k++) {
        float4 xv = *(const float4*)(xs + k * 68 + tx * 4);
        float4 w0 = *(const float4*)(ws + k * 68 + ty * 8);
        float4 w1 = *(const float4*)(ws + k * 68 + ty * 8 + 4);
        float wv[8] = {w0.x, w0.y, w0.z, w0.w, w1.x, w1.y, w1.z, w1.w};
#pragma unroll
        for (int q = 0; q < 8; q++) {
            acc[q][0] += wv[q] * xv.x;
            acc[q][1] += wv[q] * xv.y;
            acc[q][2] += wv[q] * xv.z;
            acc[q][3] += wv[q] * xv.w;
        }
    }

    float* dst = g_proj[dir] + (size_t)t * G4 * BB;
#pragma unroll
    for (int q = 0; q < 8; q++) {
        int row = r0 + ty * 8 + q;
        float bias = __ldg(bi + row);
        float4 o = make_float4(acc[q][0] + bias, acc[q][1] + bias,
                               acc[q][2] + bias, acc[q][3] + bias);
        *(float4*)(dst + (size_t)row * BB + tx * 4) = o;
    }
}

// ---------------- persistent recurrent scan ----------------
// 128 blocks (64 fwd + 64 bwd), 256 threads, 1 CTA/SM.
// Block owns j' in [j0,j0+4): W_hh rows in registers; batch packed in f32x2 pairs.
// Per-warp k-slice staging via cp.async; distributed-flag grid barrier.
__global__ void __launch_bounds__(256, 1) scan_kernel(
    const float* __restrict__ whh_f, const float* __restrict__ whh_b,
    const float* __restrict__ bhh_f, const float* __restrict__ bhh_b)
{
    extern __shared__ float smem[];
    float* h_s = smem;             // [256][64] h transposed (64KB); warp ks owns rows ks*32..+31
    float* red = smem + HB;        // [8][16][64] split-k partials (32KB)

    const int dir = blockIdx.x >> 6;
    const int blk = blockIdx.x & 63;
    const int j0  = blk * 4;
    const float* whh = dir ? whh_b : whh_f;
    const float* bhh = dir ? bhh_b : bhh_f;
    const int tid  = threadIdx.x;
    const int lane = tid & 31;

    // compute-phase mapping: warp = k-slice, lanes = 8 b-groups x 4 gates
    const int bg = tid & 7;          // b = bg*8 .. +7 (4 f32x2 pairs)
    const int rg = (tid >> 3) & 3;   // gate index
    const int ks = tid >> 5;         // k-slice [ks*32, ks*32+32)

    // W_hh registers (scalar, as R1)
    float w[4][32];
#pragma unroll
    for (int q = 0; q < 4; q++) {
        int row = rg * 256 + j0 + q;
#pragma unroll
        for (int kk = 0; kk < 32; kk++)
            w[q][kk] = __ldg(whh + (size_t)row * HH + ks * 32 + kk);
    }

    // gate/state-phase mapping
    const int jj2 = tid >> 6;        // 0..3
    const int b2  = tid & 63;        // 0..63
    float bh[4];
#pragma unroll
    for (int g = 0; g < 4; g++) bh[g] = __ldg(bhh + g * 256 + j0 + jj2);

    float c = 0.0f;
    int p = 0;
    float* hbuf = &g_hbuf[dir][0][0];
    const unsigned* fl0 = &g_flags[dir][lane][0];
    const unsigned* fl1 = &g_flags[dir][lane + 32][0];
    __syncthreads();

    for (int s = 0; s < TT; ++s) {
        const int t = dir ? (TT - 1 - s) : s;

        // prefetch x-projection gate values (DRAM; hides under poll + k-loop)
        float pf[4];
#pragma unroll
        for (int g = 0; g < 4; g++)
            pf[g] = __ldg(g_proj[dir] + ((size_t)t * G4 + g * 256 + j0 + jj2) * BB + b2);

        // per-warp wait: all 64 producer CTAs of this dir published step s-1
        {
            const unsigned tgt = (unsigned)s;
            for (;;) {
                unsigned a, b;
                asm volatile("ld.global.acquire.gpu.u32 %0, [%1];" : "=r"(a) : "l"(fl0));
                asm volatile("ld.global.acquire.gpu.u32 %0, [%1];" : "=r"(b) : "l"(fl1));
                if (__all_sync(0xffffffffu, (a >= tgt) & (b >= tgt))) break;
            }
        }

        // per-warp h staging: load own 8KB k-slice (32 rows x 64 b) via cp.async
        {
            const float* src = hbuf + p * HB + ks * 2048;
            float* dst = h_s + ks * 2048;
#pragma unroll
            for (int i = 0; i < 16; i++) {
                int off = (i * 32 + lane) * 4;
                cp_async16(dst + off, src + off);
            }
            asm volatile("cp.async.commit_group;" ::: "memory");
            asm volatile("cp.async.wait_group 0;" ::: "memory");
            __syncwarp();
        }

        // k-slice GEMM, batch pairs packed f32x2
        unsigned long long acc[4][4];
#pragma unroll
        for (int q = 0; q < 4; q++)
#pragma unroll
            for (int i = 0; i < 4; i++) acc[q][i] = 0ull;

#pragma unroll
        for (int kk = 0; kk < 32; kk++) {
            const int k = (ks << 5) + kk;
            const ulonglong2* h2 = (const ulonglong2*)(h_s + k * 64 + (bg << 3));
            ulonglong2 ha = h2[0];           // batch pairs (b0b1),(b2b3)
            ulonglong2 hc = h2[1];           // batch pairs (b4b5),(b6b7)
#pragma unroll
            for (int q = 0; q < 4; q++) {
                unsigned long long wq = pack_dup(w[q][kk]);
                ffma2(acc[q][0], wq, ha.x);
                ffma2(acc[q][1], wq, ha.y);
                ffma2(acc[q][2], wq, hc.x);
                ffma2(acc[q][3], wq, hc.y);
            }
        }

        // write split-k partials: red[ks][gate*4+q][b]
#pragma unroll
        for (int q = 0; q < 4; q++) {
            float* rp = red + ((ks << 4) + (rg << 2) + q) * 64 + (bg << 3);
            ulonglong2 u0; u0.x = acc[q][0]; u0.y = acc[q][1];
            ulonglong2 u1; u1.x = acc[q][2]; u1.y = acc[q][3];
            *(ulonglong2*)rp = u0;
            *(ulonglong2*)(rp + 4) = u1;
        }
        __syncthreads();

        // gate phase: reduce 8 partials per gate, apply LSTM cell
        float gv[4];
#pragma unroll
        for (int g = 0; g < 4; g++) {
            float v = pf[g] + bh[g];
#pragma unroll
            for (int wi = 0; wi < 8; wi++)
                v += red[((wi << 4) + (g << 2) + jj2) * 64 + b2];
            gv[g] = v;
        }
        float i_ = sigf(gv[0]);
        float f_ = sigf(gv[1]);
        float g_ = tanh_fast(gv[2]);
        float o_ = sigf(gv[3]);
        c = f_ * c + i_ * g_;
        float h = o_ * tanh_fast(c);

        // publish h + hidden sequence
        hbuf[(p ^ 1) * HB + (j0 + jj2) * 64 + b2] = h;
        g_hs[((size_t)t * 512 + dir * HH + j0 + jj2) * BB + b2] = h;

        // release own flag (distributed barrier; consumers poll per-warp)
        __syncthreads();
        if (tid == 0) {
            asm volatile("fence.acq_rel.gpu;" ::: "memory");
            asm volatile("st.global.release.gpu.u32 [%0], %1;"
                         :: "l"(&g_flags[dir][blk][0]), "r"((unsigned)(s + 1)) : "memory");
        }
        p ^= 1;
    }
}

// ---------------- final FC ----------------
__global__ void __launch_bounds__(320) fc_kernel(
    const float* __restrict__ fcw, const float* __restrict__ fcb,
    float* __restrict__ out)
{
    const int t = blockIdx.x;
    const int o = threadIdx.x / 64;  // 0..4
    const int b = threadIdx.x & 63;  // 0..63
    const float* hp = g_hs + (size_t)t * 512 * BB + b;
    const float* wp = fcw + o * 512;
    float acc = 0.0f;
#pragma unroll 8
    for (int j = 0; j < 512; j++)
        acc += hp[(size_t)j * BB] * __ldg(wp + j);
    out[((size_t)b * TT + t) * 5 + o] = acc + __ldg(fcb + o);
}

// ---------------- launch ----------------
extern "C" void kernel_launch(void* const* d_in, const int* in_sizes, int n_in,
                              void* d_out, int out_size)
{
    const float* x      = (const float*)d_in[0];
    const float* wih_f  = (const float*)d_in[1];
    const float* whh_f  = (const float*)d_in[2];
    const float* bih_f  = (const float*)d_in[3];
    const float* bhh_f  = (const float*)d_in[4];
    const float* wih_b  = (const float*)d_in[5];
    const float* whh_b  = (const float*)d_in[6];
    const float* bih_b  = (const float*)d_in[7];
    const float* bhh_b  = (const float*)d_in[8];
    const float* fcw    = (const float*)d_in[9];
    const float* fcb    = (const float*)d_in[10];
    float* out = (float*)d_out;

    const int proj_smem = 2 * 136 * 68 * (int)sizeof(float);       // 73,984 B
    const int scan_smem = (HB + 8 * 16 * 64) * (int)sizeof(float); // 98,304 B
    cudaFuncSetAttribute(proj_kernel, cudaFuncAttributeMaxDynamicSharedMemorySize, proj_smem);
    cudaFuncSetAttribute(scan_kernel, cudaFuncAttributeMaxDynamicSharedMemorySize, scan_smem);

    init_kernel<<<1, 256>>>();

    dim3 pg(16, TT, 2);
    proj_kernel<<<pg, 128, proj_smem>>>(x, wih_f, wih_b, bih_f, bih_b);

    scan_kernel<<<2 * NBLK, 256, scan_smem>>>(whh_f, whh_b, bhh_f, bhh_b);

    fc_kernel<<<TT, 320>>>(fcw, fcb, out);
}